// round 7
// baseline (speedup 1.0000x reference)
#include <cuda_runtime.h>
#include <float.h>

// Problem constants (fixed by the dataset)
#define N_  2
#define C_  256
#define H_  56
#define W_  56
#define R_  512
#define P_  7
#define SCALE_ 0.0625f
#define PLANE_ (H_ * W_)

#define CSLAB   16            // channels per block
#define TMAX    23            // max region extent (roi_dim + 1 <= 23)
#define CSTRIDE 20            // floats per cell in smem (16 ch + 4 pad; 80B, 16B-aligned)
#define DWMAX   5             // max bin window span: < bin_w + 2 <= 22/7 + 2

__global__ __launch_bounds__(256) void roipool_kernel(
    const float* __restrict__ features,
    const float* __restrict__ rois,
    float* __restrict__ out)
{
    __shared__ __align__(16) float tile[TMAX * TMAX * CSTRIDE]; // 42320 B
    __shared__ float stage[CSLAB * P_ * P_];                    // 3136 B

    const int t  = threadIdx.x;
    const int r  = blockIdx.x >> 4;            // 512 rois
    const int c0 = (blockIdx.x & 15) * CSLAB;  // 16 slabs of 16 channels

    // ---- ROI math (block-uniform; fp32 ops MUST match per-bin math) ----
    const float* roi = rois + r * 5;
    const int b  = (int)roi[0];                      // trunc == astype(int32)
    const int x1 = __float2int_rn(roi[1] * SCALE_);  // half-even == jnp.round
    const int y1 = __float2int_rn(roi[2] * SCALE_);
    const int x2 = __float2int_rn(roi[3] * SCALE_);
    const int y2 = __float2int_rn(roi[4] * SCALE_);

    const float bin_h = (float)max(y2 - y1 + 1, 1) * (1.0f / P_);
    const float bin_w = (float)max(x2 - x1 + 1, 1) * (1.0f / P_);

    // Region = [hstart(0), hend(6)) x [wstart(0), wend(6)) — exact union of
    // all bin windows (start/end monotone in p), identical float expressions.
    const int y_lo = min(max(y1, 0), H_);                                  // floor(0)+y1
    const int y_hi = min(max((int)ceilf((float)P_ * bin_h) + y1, 0), H_);
    const int x_lo = min(max(x1, 0), W_);
    const int x_hi = min(max((int)ceilf((float)P_ * bin_w) + x1, 0), W_);

    const int nrows = min(y_hi - y_lo, TMAX);   // >= 0
    const int ncols = min(x_hi - x_lo, TMAX);

    // Quad-aligned column range. W=56 % 4 == 0 and plane base is 16B-aligned,
    // so every aligned quad with start < x_hi stays inside its row.
    const int xa = x_lo & ~3;
    const int nq = (x_hi - xa + 3) >> 2;        // <= 7

    // ---- loader: LDG.128 quads -> channel-interleaved smem tile ----
    const int nseg = CSLAB * nrows;             // <= 368
    const float* fbase = features + (size_t)b * C_ * PLANE_;
    for (int s = t; s < nseg; s += 256) {
        int row = s >> 4;          // segment row
        int cc  = s & 15;          // segment channel
        const float4* src = (const float4*)(fbase + (size_t)(c0 + cc) * PLANE_
                                            + (y_lo + row) * W_ + xa);
        float* dst = tile + row * ncols * CSTRIDE + cc;
        for (int q = 0; q < nq; ++q) {          // nq block-uniform: no divergence
            float4 v = __ldg(src + q);
            int cb = xa + 4 * q - x_lo;
            if ((unsigned)(cb + 0) < (unsigned)ncols) dst[(cb + 0) * CSTRIDE] = v.x;
            if ((unsigned)(cb + 1) < (unsigned)ncols) dst[(cb + 1) * CSTRIDE] = v.y;
            if ((unsigned)(cb + 2) < (unsigned)ncols) dst[(cb + 2) * CSTRIDE] = v.z;
            if ((unsigned)(cb + 3) < (unsigned)ncols) dst[(cb + 3) * CSTRIDE] = v.w;
        }
    }
    __syncthreads();

    // ---- bin pass: thread = (bin, channel-quad); LDS.128 = 4 channels/cell ----
    if (t < P_ * P_ * 4) {                      // 196 active threads
        int bin = t >> 2;
        int g   = t & 3;                        // channel quad: c0 + 4g .. +3
        int ph  = bin / P_;
        int pw  = bin - ph * P_;

        int hs = min(max((int)floorf((float)ph       * bin_h) + y1, 0), H_);
        int he = min(max((int)ceilf ((float)(ph + 1) * bin_h) + y1, 0), H_);
        int ws = min(max((int)floorf((float)pw       * bin_w) + x1, 0), W_);
        int we = min(max((int)ceilf ((float)(pw + 1) * bin_w) + x1, 0), W_);

        int dh = he - hs, dw = we - ws;
        bool empty = (dh <= 0) || (dw <= 0);

        float4 m = make_float4(-FLT_MAX, -FLT_MAX, -FLT_MAX, -FLT_MAX);
        const float* tbase = tile + 4 * g
                           + ((hs - y_lo) * ncols + (ws - x_lo)) * CSTRIDE;
        for (int i = 0; i < dh; ++i) {          // dh <= 5, warp-max serialized
            const float* rp = tbase + i * ncols * CSTRIDE;
            #pragma unroll
            for (int j = 0; j < DWMAX; ++j) {   // predicated, branch-free
                if (j < dw) {
                    float4 v = *(const float4*)(rp + j * CSTRIDE); // LDS.128
                    m.x = fmaxf(m.x, v.x);
                    m.y = fmaxf(m.y, v.y);
                    m.z = fmaxf(m.z, v.z);
                    m.w = fmaxf(m.w, v.w);
                }
            }
        }
        if (empty) m = make_float4(0.f, 0.f, 0.f, 0.f);

        stage[(4 * g + 0) * (P_ * P_) + bin] = m.x;
        stage[(4 * g + 1) * (P_ * P_) + bin] = m.y;
        stage[(4 * g + 2) * (P_ * P_) + bin] = m.z;
        stage[(4 * g + 3) * (P_ * P_) + bin] = m.w;
    }
    __syncthreads();

    // ---- coalesced output: the (r, c0..c0+15) block is contiguous ----
    const size_t obase = ((size_t)r * C_ + c0) * (P_ * P_);
    for (int i = t; i < CSLAB * P_ * P_; i += 256)
        out[obase + i] = stage[i];
}

extern "C" void kernel_launch(void* const* d_in, const int* in_sizes, int n_in,
                              void* d_out, int out_size)
{
    const float* features = (const float*)d_in[0];
    const float* rois     = (const float*)d_in[1];
    float* out            = (float*)d_out;

    int grid = R_ * (C_ / CSLAB);   // 8192 blocks: (roi, 16-channel slab)
    roipool_kernel<<<grid, 256>>>(features, rois, out);
}

// round 8
// speedup vs baseline: 1.2044x; 1.2044x over previous
#include <cuda_runtime.h>
#include <float.h>

#define N_  2
#define C_  256
#define H_  56
#define W_  56
#define R_  512
#define P_  7
#define SCALE_ 0.0625f
#define PLANE_ (H_ * W_)      // 3136
#define RHALF  256            // rois per block (half of R_)

__global__ __launch_bounds__(256) void roipool_kernel(
    const float* __restrict__ features,
    const float* __restrict__ rois,
    float* __restrict__ out)
{
    __shared__ __align__(16) float sf [PLANE_];        // full plane      12544 B
    __shared__ float             shp[PLANE_];          // horiz pairmax   12544 B
    __shared__ int               spk[RHALF * 8];       // packed tables    8192 B

    const int t    = threadIdx.x;
    const int lane = t & 31;
    const int wrp  = t >> 5;
    const int bx   = blockIdx.x;
    const int c    = bx & 255;
    const int b    = (bx >> 8) & 1;
    const int half = bx >> 9;
    const int r0   = half * RHALF;

    // ---- phase A1: coalesced full-line plane load ----
    const float4* src = (const float4*)(features + ((size_t)b * C_ + c) * PLANE_);
    #pragma unroll
    for (int i = t; i < PLANE_ / 4; i += 256) {
        float4 v = __ldg(src + i);
        sf[4 * i + 0] = v.x;  sf[4 * i + 1] = v.y;
        sf[4 * i + 2] = v.z;  sf[4 * i + 3] = v.w;
    }

    // ---- phase A2: per-roi packed bin tables (exact reference math) ----
    {
        int rr = r0 + t;                       // t < 256 == RHALF
        const float* roi = rois + rr * 5;
        int bidx = (int)roi[0];                       // trunc == astype(int32)
        int x1 = __float2int_rn(roi[1] * SCALE_);     // half-even == jnp.round
        int y1 = __float2int_rn(roi[2] * SCALE_);
        int x2 = __float2int_rn(roi[3] * SCALE_);
        int y2 = __float2int_rn(roi[4] * SCALE_);
        float bin_h = (float)max(y2 - y1 + 1, 1) * (1.0f / P_);
        float bin_w = (float)max(x2 - x1 + 1, 1) * (1.0f / P_);
        #pragma unroll
        for (int p = 0; p < P_; ++p) {
            int hs = min(max((int)floorf((float)p       * bin_h) + y1, 0), H_);
            int he = min(max((int)ceilf ((float)(p + 1) * bin_h) + y1, 0), H_);
            int ws = min(max((int)floorf((float)p       * bin_w) + x1, 0), W_);
            int we = min(max((int)ceilf ((float)(p + 1) * bin_w) + x1, 0), W_);
            spk[t * 8 + p] = hs | (he << 8) | (ws << 16) | (we << 24);
        }
        spk[t * 8 + 7] = (bidx == b);
    }
    __syncthreads();

    // ---- phase A3: horizontal pairmax plane (hp[i] = max(f[i], f[i+1])) ----
    for (int i = t; i < PLANE_ - 1; i += 256)
        shp[i] = fmaxf(sf[i], sf[i + 1]);
    if (t == 0) shp[PLANE_ - 1] = sf[PLANE_ - 1];
    __syncthreads();

    // ---- bin pass: warp = one roi (uniform), lanes = bins, 2 passes ----
    const size_t oc = ((size_t)0 * C_ + c) * (P_ * P_);   // channel offset part
    for (int ridx = wrp; ridx < RHALF; ridx += 8) {
        if (!spk[ridx * 8 + 7]) continue;                 // warp-uniform skip

        const size_t obase = ((size_t)(r0 + ridx) * C_) * (P_ * P_) + oc;

        #pragma unroll
        for (int pass = 0; pass < 2; ++pass) {
            int q = lane + pass * 32;
            if (q < P_ * P_) {
                int ph = q / P_;
                int pw = q - ph * P_;
                int vh = spk[ridx * 8 + ph];
                int vw = spk[ridx * 8 + pw];
                int hs =  vh        & 0xFF;
                int he = (vh >> 8)  & 0xFF;
                int ws = (vw >> 16) & 0xFF;
                int we = (vw >> 24) & 0xFF;
                int dh = he - hs;
                int dw = we - ws;

                float m = -FLT_MAX;
                int base = hs * W_ + ws;
                for (int i = 0; i < dh; ++i) {            // dh <= 5
                    int ro = base + i * W_;
                    #pragma unroll
                    for (int k = 0; k < 3; ++k)           // pairs via hp
                        if (2 * k + 1 < dw) m = fmaxf(m, shp[ro + 2 * k]);
                    if (dw & 1) m = fmaxf(m, sf[ro + dw - 1]);   // odd tail
                }
                out[obase + q] = (dh > 0 && dw > 0) ? m : 0.0f;
            }
        }
    }
}

extern "C" void kernel_launch(void* const* d_in, const int* in_sizes, int n_in,
                              void* d_out, int out_size)
{
    const float* features = (const float*)d_in[0];
    const float* rois     = (const float*)d_in[1];
    float* out            = (float*)d_out;

    // grid = (image b) x (channel c) x (roi half) = 2*256*2 = 1024 blocks
    roipool_kernel<<<1024, 256>>>(features, rois, out);
}

// round 9
// speedup vs baseline: 1.2412x; 1.0305x over previous
#include <cuda_runtime.h>
#include <float.h>

#define N_  2
#define C_  256
#define H_  56
#define W_  56
#define R_  512
#define P_  7
#define SCALE_ 0.0625f
#define PLANE_ (H_ * W_)      // 3136 = 98 * 32
#define CGRP   64             // channels per main-kernel block

// NHWC scratch: g_t[b][hw][c]
__device__ float g_t[(size_t)N_ * PLANE_ * C_];

// ---------- kernel 1: NCHW -> NHWC transpose (tiled, both sides coalesced) ----------
__global__ __launch_bounds__(256) void transpose_kernel(const float* __restrict__ f)
{
    __shared__ float tile[32][33];
    const int x  = threadIdx.x & 31;       // fast index
    const int y  = threadIdx.x >> 5;       // 8 rows
    const int hw0 = blockIdx.x * 32;       // 98 tiles
    const int c0  = blockIdx.y * 32;       // 8 tiles
    const int b   = blockIdx.z;

    #pragma unroll
    for (int i = 0; i < 4; ++i) {
        int c = c0 + y + i * 8;
        tile[y + i * 8][x] = __ldg(f + ((size_t)b * C_ + c) * PLANE_ + hw0 + x);
    }
    __syncthreads();
    #pragma unroll
    for (int i = 0; i < 4; ++i) {
        int hw = hw0 + y + i * 8;
        g_t[((size_t)b * PLANE_ + hw) * C_ + c0 + x] = tile[x][y + i * 8];
    }
}

// ---------- kernel 2: pooling; warp-unit = (bin, 32-channel half), lanes = channels ----------
__global__ __launch_bounds__(256) void roipool_kernel(
    const float* __restrict__ rois,
    float* __restrict__ out)
{
    __shared__ int   sdesc[P_ * P_];          // packed per-bin window
    __shared__ int   sb;                      // roi batch index
    __shared__ float stage[CGRP * P_ * P_];   // 12544 B

    const int t    = threadIdx.x;
    const int lane = t & 31;
    const int wrp  = t >> 5;
    const int r    = blockIdx.x >> 2;         // 512 rois
    const int c0   = (blockIdx.x & 3) * CGRP; // 4 channel groups

    // ---- phase A: 49 threads build per-bin descriptors (exact reference math) ----
    if (t < P_ * P_) {
        const float* roi = rois + r * 5;
        int x1 = __float2int_rn(roi[1] * SCALE_);   // half-even == jnp.round
        int y1 = __float2int_rn(roi[2] * SCALE_);
        int x2 = __float2int_rn(roi[3] * SCALE_);
        int y2 = __float2int_rn(roi[4] * SCALE_);
        float bin_h = (float)max(y2 - y1 + 1, 1) * (1.0f / P_);
        float bin_w = (float)max(x2 - x1 + 1, 1) * (1.0f / P_);

        int ph = t / P_, pw = t - ph * P_;
        int hs = min(max((int)floorf((float)ph       * bin_h) + y1, 0), H_);
        int he = min(max((int)ceilf ((float)(ph + 1) * bin_h) + y1, 0), H_);
        int ws = min(max((int)floorf((float)pw       * bin_w) + x1, 0), W_);
        int we = min(max((int)ceilf ((float)(pw + 1) * bin_w) + x1, 0), W_);

        int dh = max(he - hs, 0);
        int dw = max(we - ws, 0);
        sdesc[t] = (hs * W_ + ws) | (dh << 16) | (dw << 22);
        if (t == 0) sb = (int)roi[0];               // trunc == astype(int32)
    }
    __syncthreads();

    // ---- phase B: 98 warp-units, everything warp-uniform except the data ----
    const int b = sb;
    for (int u = wrp; u < P_ * P_ * 2; u += 8) {
        int bin  = u >> 1;
        int half = u & 1;
        int d    = sdesc[bin];                      // LDS broadcast
        int base =  d        & 0xFFFF;
        int dh   = (d >> 16) & 0x3F;
        int dw   =  d >> 22;

        const float* p = g_t + ((size_t)b * PLANE_ + base) * C_
                       + c0 + half * 32 + lane;     // lanes: 32 consecutive ch

        float m = -FLT_MAX;
        for (int i = 0; i < dh; ++i) {              // uniform trip, <= 5
            const float* rp = p + i * (W_ * C_);
            #pragma unroll
            for (int j = 0; j < 5; ++j)             // dw <= 5 (roi_w <= 22)
                if (j < dw) m = fmaxf(m, __ldg(rp + j * C_));
            for (int j = 5; j < dw; ++j)            // safety net, never taken
                m = fmaxf(m, __ldg(rp + j * C_));
        }
        if (dh == 0 || dw == 0) m = 0.0f;

        // stride-49 store: bank = lane*49 mod 32 = permutation, conflict-free
        stage[(half * 32 + lane) * (P_ * P_) + bin] = m;
    }
    __syncthreads();

    // ---- phase C: coalesced contiguous write of the (r, c0..c0+63) block ----
    const size_t obase = ((size_t)r * C_ + c0) * (P_ * P_);
    #pragma unroll
    for (int k = 0; k < (CGRP * P_ * P_) / 256 + 1; ++k) {
        int i = t + k * 256;
        if (i < CGRP * P_ * P_) out[obase + i] = stage[i];
    }
}

extern "C" void kernel_launch(void* const* d_in, const int* in_sizes, int n_in,
                              void* d_out, int out_size)
{
    const float* features = (const float*)d_in[0];
    const float* rois     = (const float*)d_in[1];
    float* out            = (float*)d_out;

    dim3 tg(PLANE_ / 32, C_ / 32, N_);     // 98 x 8 x 2 tiles
    transpose_kernel<<<tg, 256>>>(features);

    roipool_kernel<<<R_ * (C_ / CGRP), 256>>>(rois, out);   // 2048 blocks
}

// round 10
// speedup vs baseline: 1.7912x; 1.4432x over previous
#include <cuda_runtime.h>
#include <float.h>

#define N_  2
#define C_  256
#define H_  56
#define W_  56
#define R_  512
#define P_  7
#define SCALE_ 0.0625f
#define PLANE_ (H_ * W_)      // 3136 = 98 * 32

// NHWC scratch: g_t[b][hw][c]
__device__ float g_t[(size_t)N_ * PLANE_ * C_];

// ---------- kernel 1: NCHW -> NHWC transpose (tiled, both sides coalesced) ----------
__global__ __launch_bounds__(256) void transpose_kernel(const float* __restrict__ f)
{
    __shared__ float tile[32][33];
    const int x   = threadIdx.x & 31;
    const int y   = threadIdx.x >> 5;
    const int hw0 = blockIdx.x * 32;       // 98 tiles
    const int c0  = blockIdx.y * 32;       // 8 tiles
    const int b   = blockIdx.z;

    #pragma unroll
    for (int i = 0; i < 4; ++i) {
        int c = c0 + y + i * 8;
        tile[y + i * 8][x] = __ldg(f + ((size_t)b * C_ + c) * PLANE_ + hw0 + x);
    }
    __syncthreads();
    #pragma unroll
    for (int i = 0; i < 4; ++i) {
        int hw = hw0 + y + i * 8;
        g_t[((size_t)b * PLANE_ + hw) * C_ + c0 + x] = tile[x][y + i * 8];
    }
}

// ---------- kernel 2: warp-unit = (bin, 128 channels via float4 lanes) ----------
__global__ __launch_bounds__(256) void roipool_kernel(
    const float* __restrict__ rois,
    float* __restrict__ out)
{
    __shared__ int   sdesc[P_ * P_];
    __shared__ int   sb;
    __shared__ __align__(16) float stage[128 * P_ * P_];   // 25088 B, == out layout

    const int t    = threadIdx.x;
    const int lane = t & 31;
    const int wrp  = t >> 5;
    const int r    = blockIdx.x >> 1;          // 512 rois
    const int c0   = (blockIdx.x & 1) * 128;   // C-half

    // ---- phase A: 49 threads build per-bin descriptors (exact reference math) ----
    if (t < P_ * P_) {
        const float* roi = rois + r * 5;
        int x1 = __float2int_rn(roi[1] * SCALE_);   // half-even == jnp.round
        int y1 = __float2int_rn(roi[2] * SCALE_);
        int x2 = __float2int_rn(roi[3] * SCALE_);
        int y2 = __float2int_rn(roi[4] * SCALE_);
        float bin_h = (float)max(y2 - y1 + 1, 1) * (1.0f / P_);
        float bin_w = (float)max(x2 - x1 + 1, 1) * (1.0f / P_);

        int ph = t / P_, pw = t - ph * P_;
        int hs = min(max((int)floorf((float)ph       * bin_h) + y1, 0), H_);
        int he = min(max((int)ceilf ((float)(ph + 1) * bin_h) + y1, 0), H_);
        int ws = min(max((int)floorf((float)pw       * bin_w) + x1, 0), W_);
        int we = min(max((int)ceilf ((float)(pw + 1) * bin_w) + x1, 0), W_);

        int dh = max(he - hs, 0);
        int dw = max(we - ws, 0);
        sdesc[t] = (hs * W_ + ws) | (dh << 16) | (dw << 22);
        if (t == 0) sb = (int)roi[0];               // trunc == astype(int32)
    }
    __syncthreads();

    // ---- phase B: 49 warp-units; dh/dw warp-uniform -> plain dynamic loops ----
    const int b = sb;
    for (int u = wrp; u < P_ * P_; u += 8) {
        int d    = sdesc[u];                        // LDS broadcast
        int base =  d        & 0xFFFF;
        int dh   = (d >> 16) & 0x3F;
        int dw   =  d >> 22;

        // lane covers channels c0 + 4*lane .. +3 (16B-aligned: C_=256)
        const float* p = g_t + ((size_t)b * PLANE_ + base) * C_ + c0 + 4 * lane;

        float4 m = make_float4(-FLT_MAX, -FLT_MAX, -FLT_MAX, -FLT_MAX);
        for (int i = 0; i < dh; ++i) {
            const float* rp = p + i * (W_ * C_);
            for (int j = 0; j < dw; ++j) {
                float4 v = __ldg((const float4*)(rp + j * C_));   // LDG.128
                m.x = fmaxf(m.x, v.x);
                m.y = fmaxf(m.y, v.y);
                m.z = fmaxf(m.z, v.z);
                m.w = fmaxf(m.w, v.w);
            }
        }
        if (dh == 0 || dw == 0) m = make_float4(0.f, 0.f, 0.f, 0.f);

        // stage laid out as the output block: stage[ch][bin]
        stage[(4 * lane + 0) * (P_ * P_) + u] = m.x;
        stage[(4 * lane + 1) * (P_ * P_) + u] = m.y;
        stage[(4 * lane + 2) * (P_ * P_) + u] = m.z;
        stage[(4 * lane + 3) * (P_ * P_) + u] = m.w;
    }
    __syncthreads();

    // ---- phase C: float4-coalesced copy; (r*C_+c0)*49 is a multiple of 4 ----
    const size_t obase = ((size_t)r * C_ + c0) * (P_ * P_);
    const float4* s4 = (const float4*)stage;
    float4* o4 = (float4*)(out + obase);
    #pragma unroll
    for (int k = 0; k < (128 * P_ * P_ / 4 + 255) / 256; ++k) {
        int i = t + k * 256;
        if (i < 128 * P_ * P_ / 4) o4[i] = s4[i];
    }
}

extern "C" void kernel_launch(void* const* d_in, const int* in_sizes, int n_in,
                              void* d_out, int out_size)
{
    const float* features = (const float*)d_in[0];
    const float* rois     = (const float*)d_in[1];
    float* out            = (float*)d_out;

    dim3 tg(PLANE_ / 32, C_ / 32, N_);     // 98 x 8 x 2 tiles
    transpose_kernel<<<tg, 256>>>(features);

    roipool_kernel<<<R_ * 2, 256>>>(rois, out);   // 1024 blocks: (roi, C-half)
}

// round 11
// speedup vs baseline: 1.8535x; 1.0348x over previous
#include <cuda_runtime.h>
#include <float.h>

#define N_  2
#define C_  256
#define H_  56
#define W_  56
#define R_  512
#define P_  7
#define SCALE_ 0.0625f
#define PLANE_ (H_ * W_)      // 3136 = 98 * 32
#define DWMAX  5              // dw < bin_w + 2 <= 22/7 + 2 = 5.14

// NHWC scratch: g_t[b][hw][c]
__device__ float g_t[(size_t)N_ * PLANE_ * C_];

// ---------- kernel 1: NCHW -> NHWC transpose (tiled, both sides coalesced) ----------
__global__ __launch_bounds__(256) void transpose_kernel(const float* __restrict__ f)
{
    __shared__ float tile[32][33];
    const int x   = threadIdx.x & 31;
    const int y   = threadIdx.x >> 5;
    const int hw0 = blockIdx.x * 32;       // 98 tiles
    const int c0  = blockIdx.y * 32;       // 8 tiles
    const int b   = blockIdx.z;

    #pragma unroll
    for (int i = 0; i < 4; ++i) {
        int c = c0 + y + i * 8;
        tile[y + i * 8][x] = __ldg(f + ((size_t)b * C_ + c) * PLANE_ + hw0 + x);
    }
    __syncthreads();
    #pragma unroll
    for (int i = 0; i < 4; ++i) {
        int hw = hw0 + y + i * 8;
        g_t[((size_t)b * PLANE_ + hw) * C_ + c0 + x] = tile[x][y + i * 8];
    }
}

// ---------- kernel 2: warp-unit = (bin, 128 channels via float4 lanes) ----------
__global__ __launch_bounds__(256) void roipool_kernel(
    const float* __restrict__ rois,
    float* __restrict__ out)
{
    __shared__ int   sdesc[P_ * P_];
    __shared__ int   sb;
    __shared__ __align__(16) float stage[128 * P_ * P_];   // 25088 B, == out layout

    const int t    = threadIdx.x;
    const int lane = t & 31;
    const int wrp  = t >> 5;
    const int r    = blockIdx.x >> 1;          // 512 rois
    const int c0   = (blockIdx.x & 1) * 128;   // C-half

    // ---- phase A: 49 threads build per-bin descriptors (exact reference math) ----
    if (t < P_ * P_) {
        const float* roi = rois + r * 5;
        int x1 = __float2int_rn(roi[1] * SCALE_);   // half-even == jnp.round
        int y1 = __float2int_rn(roi[2] * SCALE_);
        int x2 = __float2int_rn(roi[3] * SCALE_);
        int y2 = __float2int_rn(roi[4] * SCALE_);
        float bin_h = (float)max(y2 - y1 + 1, 1) * (1.0f / P_);
        float bin_w = (float)max(x2 - x1 + 1, 1) * (1.0f / P_);

        int ph = t / P_, pw = t - ph * P_;
        int hs = min(max((int)floorf((float)ph       * bin_h) + y1, 0), H_);
        int he = min(max((int)ceilf ((float)(ph + 1) * bin_h) + y1, 0), H_);
        int ws = min(max((int)floorf((float)pw       * bin_w) + x1, 0), W_);
        int we = min(max((int)ceilf ((float)(pw + 1) * bin_w) + x1, 0), W_);

        int dh = max(he - hs, 0);
        int dw = max(we - ws, 0);
        sdesc[t] = (hs * W_ + ws) | (dh << 16) | (dw << 22);
        if (t == 0) sb = (int)roi[0];               // trunc == astype(int32)
    }
    __syncthreads();

    // ---- phase B: 49 warp-units; dh/dw warp-uniform; row loads batched (MLP=5) ----
    const int b = sb;
    for (int u = wrp; u < P_ * P_; u += 8) {
        int d    = sdesc[u];                        // LDS broadcast
        int base =  d        & 0xFFFF;
        int dh   = (d >> 16) & 0x3F;
        int dw   =  d >> 22;

        // lane covers channels c0 + 4*lane .. +3 (16B-aligned: C_=256)
        const float* p = g_t + ((size_t)b * PLANE_ + base) * C_ + c0 + 4 * lane;

        float4 m = make_float4(-FLT_MAX, -FLT_MAX, -FLT_MAX, -FLT_MAX);
        for (int i = 0; i < dh; ++i) {              // uniform, <= 5
            const float* rp = p + i * (W_ * C_);
            // batched predicated loads: 5 LDG.128 issued back-to-back
            float4 v[DWMAX];
            #pragma unroll
            for (int j = 0; j < DWMAX; ++j)
                if (j < dw) v[j] = __ldg((const float4*)(rp + j * C_));
            #pragma unroll
            for (int j = 0; j < DWMAX; ++j)
                if (j < dw) {
                    m.x = fmaxf(m.x, v[j].x);
                    m.y = fmaxf(m.y, v[j].y);
                    m.z = fmaxf(m.z, v[j].z);
                    m.w = fmaxf(m.w, v[j].w);
                }
            for (int j = DWMAX; j < dw; ++j) {      // safety net, never taken
                float4 w = __ldg((const float4*)(rp + j * C_));
                m.x = fmaxf(m.x, w.x);  m.y = fmaxf(m.y, w.y);
                m.z = fmaxf(m.z, w.z);  m.w = fmaxf(m.w, w.w);
            }
        }
        if (dh == 0 || dw == 0) m = make_float4(0.f, 0.f, 0.f, 0.f);

        // stage laid out as the output block: stage[ch][bin]
        stage[(4 * lane + 0) * (P_ * P_) + u] = m.x;
        stage[(4 * lane + 1) * (P_ * P_) + u] = m.y;
        stage[(4 * lane + 2) * (P_ * P_) + u] = m.z;
        stage[(4 * lane + 3) * (P_ * P_) + u] = m.w;
    }
    __syncthreads();

    // ---- phase C: float4-coalesced copy; (r*C_+c0)*49 is a multiple of 4 ----
    const size_t obase = ((size_t)r * C_ + c0) * (P_ * P_);
    const float4* s4 = (const float4*)stage;
    float4* o4 = (float4*)(out + obase);
    #pragma unroll
    for (int k = 0; k < (128 * P_ * P_ / 4 + 255) / 256; ++k) {
        int i = t + k * 256;
        if (i < 128 * P_ * P_ / 4) o4[i] = s4[i];
    }
}

extern "C" void kernel_launch(void* const* d_in, const int* in_sizes, int n_in,
                              void* d_out, int out_size)
{
    const float* features = (const float*)d_in[0];
    const float* rois     = (const float*)d_in[1];
    float* out            = (float*)d_out;

    dim3 tg(PLANE_ / 32, C_ / 32, N_);     // 98 x 8 x 2 tiles
    transpose_kernel<<<tg, 256>>>(features);

    roipool_kernel<<<R_ * 2, 256>>>(rois, out);   // 1024 blocks: (roi, C-half)
}

// round 12
// speedup vs baseline: 1.8558x; 1.0012x over previous
#include <cuda_runtime.h>
#include <float.h>

#define N_  2
#define C_  256
#define H_  56
#define W_  56
#define R_  512
#define P_  7
#define SCALE_ 0.0625f
#define PLANE_ (H_ * W_)      // 3136 = 98 * 32

// NHWC tensors: [b][hw][c]
__device__ float g_t[(size_t)N_ * PLANE_ * C_];   // features
__device__ float g_h[(size_t)N_ * PLANE_ * C_];   // horiz pairmax
__device__ float g_v[(size_t)N_ * PLANE_ * C_];   // vert  pairmax
__device__ float g_2[(size_t)N_ * PLANE_ * C_];   // 2x2   pairmax

__device__ __forceinline__ float4 fmax4(float4 a, float4 b) {
    return make_float4(fmaxf(a.x,b.x), fmaxf(a.y,b.y), fmaxf(a.z,b.z), fmaxf(a.w,b.w));
}

// ---------- kernel 1: NCHW -> NHWC transpose ----------
__global__ __launch_bounds__(256) void transpose_kernel(const float* __restrict__ f)
{
    __shared__ float tile[32][33];
    const int x   = threadIdx.x & 31;
    const int y   = threadIdx.x >> 5;
    const int hw0 = blockIdx.x * 32;
    const int c0  = blockIdx.y * 32;
    const int b   = blockIdx.z;

    #pragma unroll
    for (int i = 0; i < 4; ++i)
        tile[y + i * 8][x] = __ldg(f + ((size_t)b * C_ + c0 + y + i * 8) * PLANE_ + hw0 + x);
    __syncthreads();
    #pragma unroll
    for (int i = 0; i < 4; ++i)
        g_t[((size_t)b * PLANE_ + hw0 + y + i * 8) * C_ + c0 + x] = tile[x][y + i * 8];
}

// ---------- kernel 2: pairmax pyramids (edge-clamped) ----------
__global__ __launch_bounds__(256) void pairmax_kernel()
{
    int idx = blockIdx.x * 256 + threadIdx.x;       // over N*PLANE*(C/4)
    int cq = idx & 63;
    int hw = (idx >> 6) % PLANE_;
    int b  = idx / (64 * PLANE_);
    int h = hw / W_, w = hw - h * W_;
    int wr = min(w + 1, W_ - 1);
    int hd = min(h + 1, H_ - 1);

    const float4* t4 = (const float4*)g_t;
    size_t pa  = ((size_t)b * PLANE_ + hw)            * 64 + cq;
    size_t pr  = ((size_t)b * PLANE_ + h  * W_ + wr)  * 64 + cq;
    size_t pd  = ((size_t)b * PLANE_ + hd * W_ + w )  * 64 + cq;
    size_t pdr = ((size_t)b * PLANE_ + hd * W_ + wr)  * 64 + cq;

    float4 a  = __ldg(t4 + pa);
    float4 r  = __ldg(t4 + pr);
    float4 d  = __ldg(t4 + pd);
    float4 dr = __ldg(t4 + pdr);

    float4 mh = fmax4(a, r);
    float4 mv = fmax4(a, d);
    ((float4*)g_h)[pa] = mh;
    ((float4*)g_v)[pa] = mv;
    ((float4*)g_2)[pa] = fmax4(mh, fmax4(d, dr));
}

// ---------- kernel 3: pooling; warp-unit = (bin, 128 ch), flat 9-load batch ----------
__global__ __launch_bounds__(256) void roipool_kernel(
    const float* __restrict__ rois,
    float* __restrict__ out)
{
    __shared__ int   sdesc[P_ * P_];
    __shared__ int   sb;
    __shared__ __align__(16) float stage[128 * P_ * P_];

    const int t    = threadIdx.x;
    const int lane = t & 31;
    const int wrp  = t >> 5;
    const int r    = blockIdx.x >> 1;
    const int c0   = (blockIdx.x & 1) * 128;

    if (t < P_ * P_) {
        const float* roi = rois + r * 5;
        int x1 = __float2int_rn(roi[1] * SCALE_);   // half-even == jnp.round
        int y1 = __float2int_rn(roi[2] * SCALE_);
        int x2 = __float2int_rn(roi[3] * SCALE_);
        int y2 = __float2int_rn(roi[4] * SCALE_);
        float bin_h = (float)max(y2 - y1 + 1, 1) * (1.0f / P_);
        float bin_w = (float)max(x2 - x1 + 1, 1) * (1.0f / P_);

        int ph = t / P_, pw = t - ph * P_;
        int hs = min(max((int)floorf((float)ph       * bin_h) + y1, 0), H_);
        int he = min(max((int)ceilf ((float)(ph + 1) * bin_h) + y1, 0), H_);
        int ws = min(max((int)floorf((float)pw       * bin_w) + x1, 0), W_);
        int we = min(max((int)ceilf ((float)(pw + 1) * bin_w) + x1, 0), W_);

        int dh = max(he - hs, 0);
        int dw = max(we - ws, 0);
        sdesc[t] = (hs * W_ + ws) | (dh << 16) | (dw << 22);
        if (t == 0) sb = (int)roi[0];               // trunc == astype(int32)
    }
    __syncthreads();

    const int b = sb;
    for (int u = wrp; u < P_ * P_; u += 8) {
        int d    = sdesc[u];
        int base =  d        & 0xFFFF;
        int dh   = (d >> 16) & 0x3F;
        int dw   =  d >> 22;
        int ph2 = dh >> 1, th = dh & 1;
        int pw2 = dw >> 1, tw = dw & 1;

        size_t o = ((size_t)b * PLANE_ + base) * C_ + c0 + 4 * lane;   // floats

        float4 m = make_float4(-FLT_MAX, -FLT_MAX, -FLT_MAX, -FLT_MAX);

        // 2x2 quads from g_2 (covers row-pairs x col-pairs); dh,dw <= 5 -> i,j < 2
        #pragma unroll
        for (int i = 0; i < 2; ++i)
            #pragma unroll
            for (int j = 0; j < 2; ++j)
                if (i < ph2 && j < pw2)
                    m = fmax4(m, __ldg((const float4*)(g_2 + o + (size_t)(2*i*W_ + 2*j) * C_)));
        // odd bottom row from g_h (covers col-pairs)
        #pragma unroll
        for (int j = 0; j < 2; ++j)
            if (th && j < pw2)
                m = fmax4(m, __ldg((const float4*)(g_h + o + (size_t)((dh-1)*W_ + 2*j) * C_)));
        // odd right col from g_v (covers row-pairs)
        #pragma unroll
        for (int i = 0; i < 2; ++i)
            if (tw && i < ph2)
                m = fmax4(m, __ldg((const float4*)(g_v + o + (size_t)(2*i*W_ + dw-1) * C_)));
        // odd corner from g_t
        if (th && tw)
            m = fmax4(m, __ldg((const float4*)(g_t + o + (size_t)((dh-1)*W_ + dw-1) * C_)));

        if (dh == 0 || dw == 0) m = make_float4(0.f, 0.f, 0.f, 0.f);

        stage[(4 * lane + 0) * (P_ * P_) + u] = m.x;
        stage[(4 * lane + 1) * (P_ * P_) + u] = m.y;
        stage[(4 * lane + 2) * (P_ * P_) + u] = m.z;
        stage[(4 * lane + 3) * (P_ * P_) + u] = m.w;
    }
    __syncthreads();

    const size_t obase = ((size_t)r * C_ + c0) * (P_ * P_);
    const float4* s4 = (const float4*)stage;
    float4* o4 = (float4*)(out + obase);
    #pragma unroll
    for (int k = 0; k < (128 * P_ * P_ / 4 + 255) / 256; ++k) {
        int i = t + k * 256;
        if (i < 128 * P_ * P_ / 4) o4[i] = s4[i];
    }
}

extern "C" void kernel_launch(void* const* d_in, const int* in_sizes, int n_in,
                              void* d_out, int out_size)
{
    const float* features = (const float*)d_in[0];
    const float* rois     = (const float*)d_in[1];
    float* out            = (float*)d_out;

    dim3 tg(PLANE_ / 32, C_ / 32, N_);
    transpose_kernel<<<tg, 256>>>(features);

    pairmax_kernel<<<(N_ * PLANE_ * (C_ / 4)) / 256, 256>>>();   // 1568 blocks

    roipool_kernel<<<R_ * 2, 256>>>(rois, out);
}